// round 3
// baseline (speedup 1.0000x reference)
#include <cuda_runtime.h>
#include <cstdint>
#include <cstddef>

#define NNODES 8192
#define DDIM   16
#define BATCH  4
#define NC     64                       // B*D output columns
#define MT     128                      // M tile
#define KT     32                       // K per stage
#define SPLITS 4
#define KRANGE (NNODES / SPLITS)        // 2048
#define NIT    (KRANGE / KT)            // 64
#define NMT    (NNODES / MT)            // 64

#define ROWF   36                       // padded floats per smem row (144B, 16B-aligned, conflict-free)
#define ROWB   (ROWF * 4)
#define A_BYTES (MT * ROWB)             // 18432
#define X_BYTES (NC * ROWB)             // 9216
#define STAGE_BYTES (A_BYTES + X_BYTES) // 27648
#define SMEM_TOTAL  (2 * STAGE_BYTES)   // 55296

__device__ __align__(128) float g_XT[NC * NNODES];             // 2 MB, tf32-rounded
__device__ __align__(128) float g_part[SPLITS * NNODES * NC];  // 8 MB

// ---- helpers ----
__device__ __forceinline__ uint32_t smem_u32(const void* p) {
    uint32_t a;
    asm("{ .reg .u64 t; cvta.to.shared.u64 t, %1; cvt.u32.u64 %0, t; }" : "=r"(a) : "l"(p));
    return a;
}
__device__ __forceinline__ uint32_t rna_tf32(float x) {
    uint32_t r;
    asm("cvt.rna.tf32.f32 %0, %1;" : "=r"(r) : "f"(x));
    return r;
}
__device__ __forceinline__ void cp_async16(uint32_t smem_dst, const void* gmem_src) {
    asm volatile("cp.async.cg.shared.global [%0], [%1], 16;" :: "r"(smem_dst), "l"(gmem_src));
}
#define CP_COMMIT() asm volatile("cp.async.commit_group;" ::: "memory")

__device__ __forceinline__ void mma_tf32(float* c, const uint32_t* a, const uint32_t* b) {
    asm volatile(
        "mma.sync.aligned.m16n8k8.row.col.f32.tf32.tf32.f32 "
        "{%0,%1,%2,%3}, {%4,%5,%6,%7}, {%8,%9}, {%0,%1,%2,%3};"
        : "+f"(c[0]), "+f"(c[1]), "+f"(c[2]), "+f"(c[3])
        : "r"(a[0]), "r"(a[1]), "r"(a[2]), "r"(a[3]), "r"(b[0]), "r"(b[1]));
}

// ---------------- kernel 1: XT[b*16+d][m] = rna_tf32(h[b][m*16+d]) ----------------
__global__ void __launch_bounds__(256) transpose_kernel(const float* __restrict__ h) {
    __shared__ float tile[16][514];
    int tid = threadIdx.x;
    int b  = blockIdx.x >> 4;
    int m0 = (blockIdx.x & 15) << 9;   // *512
    const float* src = h + (size_t)b * (NNODES * DDIM) + (size_t)m0 * DDIM;
#pragma unroll
    for (int i = 0; i < 32; i++) {
        int j = i * 256 + tid;
        tile[j & 15][j >> 4] = src[j];
    }
    __syncthreads();
#pragma unroll
    for (int i = 0; i < 32; i++) {
        int j = i * 256 + tid;
        int d = j >> 9, m = j & 511;
        g_XT[(size_t)(b * 16 + d) * NNODES + m0 + m] = __uint_as_float(rna_tf32(tile[d][m]));
    }
}

// ---------------- kernel 2: tf32 mma.sync GEMM -> g_part ----------------
// C[m][c] = sum_k A[m][k] * XT[c][k], M-tile 128, N=64, K-tile 32, split-K 4.
// 8 warps: warp_m = wid&3 (32 rows), warp_n = wid>>2 (32 cols).
__global__ void __launch_bounds__(256, 2) gemm_kernel(const float* __restrict__ A) {
    extern __shared__ char smem[];
    uint32_t sb = smem_u32(smem);
    float* sA[2] = { (float*)(smem),               (float*)(smem + STAGE_BYTES) };
    float* sX[2] = { (float*)(smem + A_BYTES),     (float*)(smem + STAGE_BYTES + A_BYTES) };

    int tid   = threadIdx.x;
    int n0    = blockIdx.x * MT;       // node-row base
    int split = blockIdx.y;
    int kbase = split * KRANGE;

    int lane = tid & 31, wid = tid >> 5;
    int wm = wid & 3, wn = wid >> 2;
    int qrow = lane >> 2, qcol = lane & 3;

    // per-thread cp.async coords
    uint32_t offA[4]; size_t gofA[4];
#pragma unroll
    for (int i = 0; i < 4; i++) {
        int q = i * 256 + tid;                 // 1024 chunks: 128 rows x 8
        int row = q >> 3, c16 = q & 7;
        offA[i] = (uint32_t)(row * ROWB + c16 * 16);
        gofA[i] = (size_t)(n0 + row) * NNODES + (size_t)c16 * 4;
    }
    uint32_t offX[2]; size_t gofX[2];
#pragma unroll
    for (int i = 0; i < 2; i++) {
        int q = i * 256 + tid;                 // 512 chunks: 64 rows x 8
        int row = q >> 3, c16 = q & 7;
        offX[i] = (uint32_t)(row * ROWB + c16 * 16);
        gofX[i] = (size_t)row * NNODES + (size_t)c16 * 4;
    }

    // prologue: tiles 0,1 -> slots 0,1
#pragma unroll
    for (int s = 0; s < 2; s++) {
        int k0 = kbase + s * KT;
        uint32_t ab = sb + s * STAGE_BYTES;
        uint32_t xb = ab + A_BYTES;
#pragma unroll
        for (int i = 0; i < 4; i++) cp_async16(ab + offA[i], A + gofA[i] + k0);
#pragma unroll
        for (int i = 0; i < 2; i++) cp_async16(xb + offX[i], g_XT + gofX[i] + k0);
        CP_COMMIT();
    }

    float acc[2][4][4];
#pragma unroll
    for (int mf = 0; mf < 2; mf++)
#pragma unroll
        for (int nf = 0; nf < 4; nf++)
#pragma unroll
            for (int r = 0; r < 4; r++) acc[mf][nf][r] = 0.0f;

    const int arow0 = wm * 32 + qrow;          // A fragment base row
    const int xrow0 = wn * 32 + qrow;          // X fragment base row (n)

    for (int it = 0; it < NIT; it++) {
        int s = it & 1;
        asm volatile("cp.async.wait_group 1;" ::: "memory");
        __syncthreads();

        const float* As = sA[s];
        const float* Xs = sX[s];
#pragma unroll
        for (int kf = 0; kf < 4; kf++) {
            int k0 = kf * 8 + qcol;
            uint32_t a[2][4];
#pragma unroll
            for (int mf = 0; mf < 2; mf++) {
                int r = arow0 + mf * 16;
                a[mf][0] = rna_tf32(As[r * ROWF + k0]);
                a[mf][1] = rna_tf32(As[(r + 8) * ROWF + k0]);
                a[mf][2] = rna_tf32(As[r * ROWF + k0 + 4]);
                a[mf][3] = rna_tf32(As[(r + 8) * ROWF + k0 + 4]);
            }
            uint32_t b[4][2];
#pragma unroll
            for (int nf = 0; nf < 4; nf++) {
                int c = xrow0 + nf * 8;
                b[nf][0] = __float_as_uint(Xs[c * ROWF + k0]);       // pre-rounded
                b[nf][1] = __float_as_uint(Xs[c * ROWF + k0 + 4]);
            }
#pragma unroll
            for (int mf = 0; mf < 2; mf++)
#pragma unroll
                for (int nf = 0; nf < 4; nf++)
                    mma_tf32(acc[mf][nf], a[mf], b[nf]);
        }
        __syncthreads();   // all reads of slot s done before refill

        int nt = it + 2; if (nt >= NIT) nt -= NIT;   // tail wraps (harmless reload)
        int k0 = kbase + nt * KT;
        uint32_t ab = sb + s * STAGE_BYTES;
        uint32_t xb = ab + A_BYTES;
#pragma unroll
        for (int i = 0; i < 4; i++) cp_async16(ab + offA[i], A + gofA[i] + k0);
#pragma unroll
        for (int i = 0; i < 2; i++) cp_async16(xb + offX[i], g_XT + gofX[i] + k0);
        CP_COMMIT();
    }
    asm volatile("cp.async.wait_group 0;" ::: "memory");

    // epilogue: direct global stores (float2 pairs, cols 2*qcol, 2*qcol+1)
#pragma unroll
    for (int mf = 0; mf < 2; mf++)
#pragma unroll
        for (int nf = 0; nf < 4; nf++) {
            int m = n0 + wm * 32 + mf * 16 + qrow;
            int c = wn * 32 + nf * 8 + qcol * 2;
            float* p0 = g_part + ((size_t)split * NNODES + m) * NC + c;
            *(float2*)p0 = make_float2(acc[mf][nf][0], acc[mf][nf][1]);
            float* p1 = g_part + ((size_t)split * NNODES + m + 8) * NC + c;
            *(float2*)p1 = make_float2(acc[mf][nf][2], acc[mf][nf][3]);
        }
}

// ---------------- kernel 3: fused MLPs ----------------
__global__ void __launch_bounds__(256) mlp_kernel(
    const float* __restrict__ h, const float* __restrict__ t,
    const float* __restrict__ W1f, const float* __restrict__ b1f,
    const float* __restrict__ W2f, const float* __restrict__ b2f,
    const float* __restrict__ W1g, const float* __restrict__ b1g,
    const float* __restrict__ W2g, const float* __restrict__ b2g,
    float* __restrict__ out) {
    __shared__ float sW1f[17 * 64], sW2f[64 * 16], sW1g[17 * 64], sW2g[64 * 16];
    __shared__ float sb1f[64], sb1g[64], sb2f[16], sb2g[16];
    int tid = threadIdx.x;
    for (int i = tid; i < 17 * 64; i += 256) { sW1f[i] = W1f[i]; sW1g[i] = W1g[i]; }
    for (int i = tid; i < 64 * 16; i += 256) { sW2f[i] = W2f[i]; sW2g[i] = W2g[i]; }
    if (tid < 64) { sb1f[tid] = b1f[tid]; sb1g[tid] = b1g[tid]; }
    if (tid < 16) { sb2f[tid] = b2f[tid]; sb2g[tid] = b2g[tid]; }
    __syncthreads();

    float tv = t[0];
    int gid = blockIdx.x * 256 + tid;       // 0..32767
    int b = gid >> 13, n = gid & (NNODES - 1);

    float x[16], y[16];
    {
        size_t base = (size_t)n * NC + (size_t)b * DDIM;
        const float4* p0 = (const float4*)(g_part + base);
        const float4* p1 = (const float4*)(g_part + (size_t)1 * NNODES * NC + base);
        const float4* p2 = (const float4*)(g_part + (size_t)2 * NNODES * NC + base);
        const float4* p3 = (const float4*)(g_part + (size_t)3 * NNODES * NC + base);
#pragma unroll
        for (int k = 0; k < 4; k++) {
            float4 a = p0[k], bb = p1[k], c = p2[k], d = p3[k];
            x[4 * k + 0] = a.x + bb.x + c.x + d.x;
            x[4 * k + 1] = a.y + bb.y + c.y + d.y;
            x[4 * k + 2] = a.z + bb.z + c.z + d.z;
            x[4 * k + 3] = a.w + bb.w + c.w + d.w;
        }
        const float4* ph = (const float4*)(h + (size_t)b * NNODES * DDIM + (size_t)n * DDIM);
#pragma unroll
        for (int k = 0; k < 4; k++) {
            float4 a = ph[k];
            y[4 * k + 0] = a.x; y[4 * k + 1] = a.y; y[4 * k + 2] = a.z; y[4 * k + 3] = a.w;
        }
    }

    float drift[16], dacc[16];
#pragma unroll
    for (int d = 0; d < 16; d++) { drift[d] = sb2f[d]; dacc[d] = sb2g[d]; }

    for (int j = 0; j < 64; j++) {
        float zf = sb1f[j] + tv * sW1f[16 * 64 + j];
        float zg = sb1g[j] + tv * sW1g[16 * 64 + j];
#pragma unroll
        for (int i = 0; i < 16; i++) {
            zf = fmaf(x[i], sW1f[i * 64 + j], zf);
            zg = fmaf(y[i], sW1g[i * 64 + j], zg);
        }
        float af = tanhf(zf);
        float ag = 1.0f / (1.0f + __expf(-zg));
#pragma unroll
        for (int d = 0; d < 16; d++) {
            drift[d] = fmaf(af, sW2f[j * 16 + d], drift[d]);
            dacc[d]  = fmaf(ag, sW2g[j * 16 + d], dacc[d]);
        }
    }

    size_t o0 = (size_t)b * NNODES * DDIM + (size_t)n * DDIM;
    float4* od = (float4*)(out + o0);
    float4* og = (float4*)(out + (size_t)BATCH * NNODES * DDIM + o0);
#pragma unroll
    for (int k = 0; k < 4; k++) {
        od[k] = make_float4(drift[4 * k], drift[4 * k + 1], drift[4 * k + 2], drift[4 * k + 3]);
        float g0 = 0.1f / (1.0f + __expf(-dacc[4 * k + 0]));
        float g1 = 0.1f / (1.0f + __expf(-dacc[4 * k + 1]));
        float g2 = 0.1f / (1.0f + __expf(-dacc[4 * k + 2]));
        float g3 = 0.1f / (1.0f + __expf(-dacc[4 * k + 3]));
        og[k] = make_float4(g0, g1, g2, g3);
    }
}

extern "C" void kernel_launch(void* const* d_in, const int* in_sizes, int n_in,
                              void* d_out, int out_size) {
    (void)in_sizes; (void)n_in; (void)out_size;
    const float* h   = (const float*)d_in[0];
    const float* t   = (const float*)d_in[1];
    const float* A   = (const float*)d_in[2];
    const float* W1f = (const float*)d_in[3];
    const float* b1f = (const float*)d_in[4];
    const float* W2f = (const float*)d_in[5];
    const float* b2f = (const float*)d_in[6];
    const float* W1g = (const float*)d_in[7];
    const float* b1g = (const float*)d_in[8];
    const float* W2g = (const float*)d_in[9];
    const float* b2g = (const float*)d_in[10];
    float* out = (float*)d_out;

    cudaFuncSetAttribute(gemm_kernel, cudaFuncAttributeMaxDynamicSharedMemorySize, SMEM_TOTAL);

    transpose_kernel<<<64, 256>>>(h);
    gemm_kernel<<<dim3(NMT, SPLITS), 256, SMEM_TOTAL>>>(A);
    mlp_kernel<<<128, 256>>>(h, t, W1f, b1f, W2f, b2f, W1g, b1g, W2g, b2g, out);
}

// round 4
// speedup vs baseline: 1.3881x; 1.3881x over previous
#include <cuda_runtime.h>
#include <cuda_bf16.h>
#include <cstdint>
#include <cstddef>

#define NNODES 8192
#define DDIM   16
#define BATCH  4
#define NC     64                       // B*D output columns
#define MT     128                      // M tile
#define KT     32                       // K per stage
#define SPLITS 4
#define KRANGE (NNODES / SPLITS)        // 2048
#define NIT    (KRANGE / KT)            // 64
#define NMT    (NNODES / MT)            // 64
#define STAGES 4

#define AROWB  160                      // A smem row bytes (32 fp32 + pad) - LDS.64 conflict-free
#define XROWB  80                       // X smem row bytes (32 bf16 + pad) - LDS.32 conflict-free
#define A_BYTES (MT * AROWB)            // 20480
#define X_BYTES (NC * XROWB)            // 5120
#define STAGE_BYTES (A_BYTES + X_BYTES) // 25600
#define SMEM_TOTAL  (STAGES * STAGE_BYTES) // 102400

__device__ __align__(128) __nv_bfloat16 g_XT[NC * NNODES];     // 1 MB, bf16-rounded
__device__ __align__(128) float g_part[SPLITS * NNODES * NC];  // 8 MB

// ---- helpers ----
__device__ __forceinline__ uint32_t smem_u32(const void* p) {
    uint32_t a;
    asm("{ .reg .u64 t; cvta.to.shared.u64 t, %1; cvt.u32.u64 %0, t; }" : "=r"(a) : "l"(p));
    return a;
}
__device__ __forceinline__ void cp_async16(uint32_t smem_dst, const void* gmem_src) {
    asm volatile("cp.async.cg.shared.global [%0], [%1], 16;" :: "r"(smem_dst), "l"(gmem_src));
}
#define CP_COMMIT() asm volatile("cp.async.commit_group;" ::: "memory")

__device__ __forceinline__ uint32_t bf2(float lo, float hi) {
    __nv_bfloat162 v = __float22bfloat162_rn(make_float2(lo, hi));  // .x -> low half
    return *(uint32_t*)&v;
}

__device__ __forceinline__ void mma_bf16(float* c, const uint32_t* a, const uint32_t* b) {
    asm volatile(
        "mma.sync.aligned.m16n8k16.row.col.f32.bf16.bf16.f32 "
        "{%0,%1,%2,%3}, {%4,%5,%6,%7}, {%8,%9}, {%0,%1,%2,%3};"
        : "+f"(c[0]), "+f"(c[1]), "+f"(c[2]), "+f"(c[3])
        : "r"(a[0]), "r"(a[1]), "r"(a[2]), "r"(a[3]), "r"(b[0]), "r"(b[1]));
}

// ---------------- kernel 1: XT[b*16+d][m] = bf16(h[b][m*16+d]) ----------------
__global__ void __launch_bounds__(256) transpose_kernel(const float* __restrict__ h) {
    __shared__ float tile[16][130];
    int tid = threadIdx.x;
    int b  = blockIdx.x >> 6;
    int m0 = (blockIdx.x & 63) << 7;   // *128
    const float* src = h + (size_t)b * (NNODES * DDIM) + (size_t)m0 * DDIM;
#pragma unroll
    for (int i = 0; i < 8; i++) {
        int j = i * 256 + tid;                 // 2048 floats, coalesced
        tile[j & 15][j >> 4] = src[j];
    }
    __syncthreads();
#pragma unroll
    for (int i = 0; i < 4; i++) {
        int j = i * 256 + tid;                 // 1024 bf16x2 writes
        int d = j >> 6, mp = j & 63;
        __nv_bfloat162 v = __float22bfloat162_rn(
            make_float2(tile[d][2 * mp], tile[d][2 * mp + 1]));
        *(__nv_bfloat162*)(g_XT + (size_t)(b * 16 + d) * NNODES + m0 + 2 * mp) = v;
    }
}

// ---------------- kernel 2: bf16 mma.sync GEMM -> g_part ----------------
// C[m][c] = sum_k A[m][k] * XT[c][k].  8 warps: wm=wid&3 (32 rows), wn=wid>>2 (32 cols).
__global__ void __launch_bounds__(256, 2) gemm_kernel(const float* __restrict__ A) {
    extern __shared__ char smem[];
    uint32_t sb = smem_u32(smem);

    int tid   = threadIdx.x;
    int n0    = blockIdx.x * MT;
    int split = blockIdx.y;
    int kbase = split * KRANGE;

    int lane = tid & 31, wid = tid >> 5;
    int wm = wid & 3, wn = wid >> 2;
    int qrow = lane >> 2, qcol = lane & 3;

    // cp.async coords: A = 1024 16B chunks (128 rows x 8), X = 256 chunks (64 rows x 4)
    uint32_t offA[4]; size_t gofA[4];
#pragma unroll
    for (int i = 0; i < 4; i++) {
        int q = i * 256 + tid;
        int row = q >> 3, c16 = q & 7;
        offA[i] = (uint32_t)(row * AROWB + c16 * 16);
        gofA[i] = (size_t)(n0 + row) * NNODES + (size_t)c16 * 4;   // floats
    }
    uint32_t offX; size_t gofX;
    {
        int row = tid >> 2, c16 = tid & 3;
        offX = (uint32_t)(row * XROWB + c16 * 16);
        gofX = (size_t)row * NNODES + (size_t)c16 * 8;             // bf16 elems
    }

    // prologue: tiles 0..2 -> slots 0..2
#pragma unroll
    for (int s = 0; s < STAGES - 1; s++) {
        int k0 = kbase + s * KT;
        uint32_t ab = sb + s * STAGE_BYTES;
#pragma unroll
        for (int i = 0; i < 4; i++) cp_async16(ab + offA[i], A + gofA[i] + k0);
        cp_async16(ab + A_BYTES + offX, g_XT + gofX + k0);
        CP_COMMIT();
    }

    float acc[2][4][4];
#pragma unroll
    for (int mf = 0; mf < 2; mf++)
#pragma unroll
        for (int nf = 0; nf < 4; nf++)
#pragma unroll
            for (int r = 0; r < 4; r++) acc[mf][nf][r] = 0.0f;

    const int arow0 = wm * 32 + qrow;
    const int xrow0 = wn * 32 + qrow;

    for (int it = 0; it < NIT; it++) {
        int slot = it & (STAGES - 1);
        asm volatile("cp.async.wait_group %0;" :: "n"(STAGES - 2) : "memory");
        __syncthreads();

        // refill first (hide latency), slot (it+3)&3 was freed at iter it-1
        int nt = it + STAGES - 1;
        if (nt < NIT) {
            int k0 = kbase + nt * KT;
            uint32_t ab = sb + (nt & (STAGES - 1)) * STAGE_BYTES;
#pragma unroll
            for (int i = 0; i < 4; i++) cp_async16(ab + offA[i], A + gofA[i] + k0);
            cp_async16(ab + A_BYTES + offX, g_XT + gofX + k0);
        }
        CP_COMMIT();

        const float* As = (const float*)(smem + slot * STAGE_BYTES);
        const char*  Xs = smem + slot * STAGE_BYTES + A_BYTES;
#pragma unroll
        for (int kk = 0; kk < 2; kk++) {
            int kb = kk * 16;
            uint32_t a[2][4];
#pragma unroll
            for (int mf = 0; mf < 2; mf++) {
                int r = arow0 + mf * 16;
                float2 p0 = *(const float2*)(As + (size_t)r * 40 + kb + 2 * qcol);
                float2 p1 = *(const float2*)(As + (size_t)(r + 8) * 40 + kb + 2 * qcol);
                float2 p2 = *(const float2*)(As + (size_t)r * 40 + kb + 2 * qcol + 8);
                float2 p3 = *(const float2*)(As + (size_t)(r + 8) * 40 + kb + 2 * qcol + 8);
                a[mf][0] = bf2(p0.x, p0.y);
                a[mf][1] = bf2(p1.x, p1.y);
                a[mf][2] = bf2(p2.x, p2.y);
                a[mf][3] = bf2(p3.x, p3.y);
            }
            uint32_t b[4][2];
#pragma unroll
            for (int nf = 0; nf < 4; nf++) {
                int c = xrow0 + nf * 8;
                b[nf][0] = *(const uint32_t*)(Xs + c * XROWB + (kb + 2 * qcol) * 2);
                b[nf][1] = *(const uint32_t*)(Xs + c * XROWB + (kb + 2 * qcol) * 2 + 16);
            }
#pragma unroll
            for (int mf = 0; mf < 2; mf++)
#pragma unroll
                for (int nf = 0; nf < 4; nf++)
                    mma_bf16(acc[mf][nf], a[mf], b[nf]);
        }
    }

    // epilogue
#pragma unroll
    for (int mf = 0; mf < 2; mf++)
#pragma unroll
        for (int nf = 0; nf < 4; nf++) {
            int m = n0 + wm * 32 + mf * 16 + qrow;
            int c = wn * 32 + nf * 8 + qcol * 2;
            float* p0 = g_part + ((size_t)split * NNODES + m) * NC + c;
            *(float2*)p0 = make_float2(acc[mf][nf][0], acc[mf][nf][1]);
            float* p1 = g_part + ((size_t)split * NNODES + m + 8) * NC + c;
            *(float2*)p1 = make_float2(acc[mf][nf][2], acc[mf][nf][3]);
        }
}

// ---------------- kernel 3: fused MLPs ----------------
__global__ void __launch_bounds__(256) mlp_kernel(
    const float* __restrict__ h, const float* __restrict__ t,
    const float* __restrict__ W1f, const float* __restrict__ b1f,
    const float* __restrict__ W2f, const float* __restrict__ b2f,
    const float* __restrict__ W1g, const float* __restrict__ b1g,
    const float* __restrict__ W2g, const float* __restrict__ b2g,
    float* __restrict__ out) {
    __shared__ float sW1f[17 * 64], sW2f[64 * 16], sW1g[17 * 64], sW2g[64 * 16];
    __shared__ float sb1f[64], sb1g[64], sb2f[16], sb2g[16];
    int tid = threadIdx.x;
    for (int i = tid; i < 17 * 64; i += 256) { sW1f[i] = W1f[i]; sW1g[i] = W1g[i]; }
    for (int i = tid; i < 64 * 16; i += 256) { sW2f[i] = W2f[i]; sW2g[i] = W2g[i]; }
    if (tid < 64) { sb1f[tid] = b1f[tid]; sb1g[tid] = b1g[tid]; }
    if (tid < 16) { sb2f[tid] = b2f[tid]; sb2g[tid] = b2g[tid]; }
    __syncthreads();

    float tv = t[0];
    int gid = blockIdx.x * 256 + tid;
    int b = gid >> 13, n = gid & (NNODES - 1);

    float x[16], y[16];
    {
        size_t base = (size_t)n * NC + (size_t)b * DDIM;
        const float4* p0 = (const float4*)(g_part + base);
        const float4* p1 = (const float4*)(g_part + (size_t)1 * NNODES * NC + base);
        const float4* p2 = (const float4*)(g_part + (size_t)2 * NNODES * NC + base);
        const float4* p3 = (const float4*)(g_part + (size_t)3 * NNODES * NC + base);
#pragma unroll
        for (int k = 0; k < 4; k++) {
            float4 a = p0[k], bb = p1[k], c = p2[k], d = p3[k];
            x[4 * k + 0] = a.x + bb.x + c.x + d.x;
            x[4 * k + 1] = a.y + bb.y + c.y + d.y;
            x[4 * k + 2] = a.z + bb.z + c.z + d.z;
            x[4 * k + 3] = a.w + bb.w + c.w + d.w;
        }
        const float4* ph = (const float4*)(h + (size_t)b * NNODES * DDIM + (size_t)n * DDIM);
#pragma unroll
        for (int k = 0; k < 4; k++) {
            float4 a = ph[k];
            y[4 * k + 0] = a.x; y[4 * k + 1] = a.y; y[4 * k + 2] = a.z; y[4 * k + 3] = a.w;
        }
    }

    float drift[16], dacc[16];
#pragma unroll
    for (int d = 0; d < 16; d++) { drift[d] = sb2f[d]; dacc[d] = sb2g[d]; }

    for (int j = 0; j < 64; j++) {
        float zf = sb1f[j] + tv * sW1f[16 * 64 + j];
        float zg = sb1g[j] + tv * sW1g[16 * 64 + j];
#pragma unroll
        for (int i = 0; i < 16; i++) {
            zf = fmaf(x[i], sW1f[i * 64 + j], zf);
            zg = fmaf(y[i], sW1g[i * 64 + j], zg);
        }
        float af = 1.0f - 2.0f / (__expf(2.0f * zf) + 1.0f);   // tanh via MUFU exp
        float ag = 1.0f / (1.0f + __expf(-zg));
#pragma unroll
        for (int d = 0; d < 16; d++) {
            drift[d] = fmaf(af, sW2f[j * 16 + d], drift[d]);
            dacc[d]  = fmaf(ag, sW2g[j * 16 + d], dacc[d]);
        }
    }

    size_t o0 = (size_t)b * NNODES * DDIM + (size_t)n * DDIM;
    float4* od = (float4*)(out + o0);
    float4* og = (float4*)(out + (size_t)BATCH * NNODES * DDIM + o0);
#pragma unroll
    for (int k = 0; k < 4; k++) {
        od[k] = make_float4(drift[4 * k], drift[4 * k + 1], drift[4 * k + 2], drift[4 * k + 3]);
        float g0 = 0.1f / (1.0f + __expf(-dacc[4 * k + 0]));
        float g1 = 0.1f / (1.0f + __expf(-dacc[4 * k + 1]));
        float g2 = 0.1f / (1.0f + __expf(-dacc[4 * k + 2]));
        float g3 = 0.1f / (1.0f + __expf(-dacc[4 * k + 3]));
        og[k] = make_float4(g0, g1, g2, g3);
    }
}

extern "C" void kernel_launch(void* const* d_in, const int* in_sizes, int n_in,
                              void* d_out, int out_size) {
    (void)in_sizes; (void)n_in; (void)out_size;
    const float* h   = (const float*)d_in[0];
    const float* t   = (const float*)d_in[1];
    const float* A   = (const float*)d_in[2];
    const float* W1f = (const float*)d_in[3];
    const float* b1f = (const float*)d_in[4];
    const float* W2f = (const float*)d_in[5];
    const float* b2f = (const float*)d_in[6];
    const float* W1g = (const float*)d_in[7];
    const float* b1g = (const float*)d_in[8];
    const float* W2g = (const float*)d_in[9];
    const float* b2g = (const float*)d_in[10];
    float* out = (float*)d_out;

    cudaFuncSetAttribute(gemm_kernel, cudaFuncAttributeMaxDynamicSharedMemorySize, SMEM_TOTAL);

    transpose_kernel<<<256, 256>>>(h);
    gemm_kernel<<<dim3(NMT, SPLITS), 256, SMEM_TOTAL>>>(A);
    mlp_kernel<<<128, 256>>>(h, t, W1f, b1f, W2f, b2f, W1g, b1g, W2g, b2g, out);
}